// round 14
// baseline (speedup 1.0000x reference)
#include <cuda_runtime.h>
#include <math.h>

// ---------------- problem constants ----------------
#define BB    1024
#define NN_   80
#define CC    51     // OUTP
#define DM_   26
#define NEGV  -1e30f

#define DIST_OFF 16384
#define A_OFF    (16384 + 1024*6400)

typedef unsigned long long u64;

// ---------------- f32x2 packed helpers ----------------
__device__ __forceinline__ u64 pk2(float lo, float hi) {
    u64 r; asm("mov.b64 %0,{%1,%2};" : "=l"(r) : "f"(lo), "f"(hi)); return r;
}
__device__ __forceinline__ u64 dup2(float v) { return pk2(v, v); }
__device__ __forceinline__ void up2(u64 v, float& a, float& b) {
    asm("mov.b64 {%0,%1},%2;" : "=f"(a), "=f"(b) : "l"(v));
}
__device__ __forceinline__ u64 fma2(u64 a, u64 b, u64 c) {
    u64 d; asm("fma.rn.f32x2 %0,%1,%2,%3;" : "=l"(d) : "l"(a), "l"(b), "l"(c)); return d;
}
__device__ __forceinline__ float f4c(const float4& v, int kk) {
    return (kk == 0) ? v.x : (kk == 1) ? v.y : (kk == 2) ? v.z : v.w;
}

// ---------------- device scratch / prepped constants ----------------
__device__ float g_x[BB * NN_ * CC];
__device__ float g_An11[64 * 64];
__device__ float g_An22[16 * 16];
__device__ unsigned int g_AtmBits[32];
__device__ float g_Wg1aT[52 * 64];   // [k][o], row 51 zero
__device__ float g_Wg2aT[51 * 64];   // [k][o]
__device__ float g_Wg1bT[64 * 64];   // [h][o2], o2>=50 zero
__device__ float g_thetaB[52 * 64];  // [c][r], r>=50 zero, rows 50,51 zero
__device__ float g_coef;

// =====================================================================
// setup work: executed by one extra block of k_mlp (256 threads)
// =====================================================================
__device__ void do_setup(float* sh,
                         const float* __restrict__ M, const float* __restrict__ Wk,
                         const float* __restrict__ smoothing,
                         const float* __restrict__ Wg1a, const float* __restrict__ Wg1b,
                         const float* __restrict__ Wg2a,
                         float* __restrict__ outA)
{
    float* sM = sh;                 // 80*26
    float* sA = sM + NN_ * DM_;     // 80*80
    float* d1 = sA + NN_ * NN_;     // 64
    float* d2 = d1 + 64;            // 16
    const int tid = threadIdx.x;
    const int lane = tid & 31, warp = tid >> 5;

    for (int e = tid; e < NN_ * DM_; e += 256) sM[e] = M[e];
    for (int e = tid; e < NN_ * NN_; e += 256) sA[e] = 0.f;
    __syncthreads();

    for (int p = warp; p < NN_; p += 8) {
        float vals[3];
        float mx = NEGV;
        int cnt = 0;
        for (int q = lane; q < p; q += 32) {
            float s = 0.f;
            #pragma unroll
            for (int k = 0; k < DM_; k++) s = fmaf(sM[p * DM_ + k], sM[q * DM_ + k], s);
            s = fmaxf(s, 0.f);
            vals[cnt++] = s;
            mx = fmaxf(mx, s);
        }
        #pragma unroll
        for (int off = 16; off; off >>= 1) mx = fmaxf(mx, __shfl_xor_sync(0xffffffffu, mx, off));
        float sum = 0.f;
        for (int c = 0; c < cnt; c++) { vals[c] = expf(vals[c] - mx); sum += vals[c]; }
        #pragma unroll
        for (int off = 16; off; off >>= 1) sum += __shfl_xor_sync(0xffffffffu, sum, off);
        float inv = (p > 0) ? 1.f / sum : 0.f;
        cnt = 0;
        for (int q = lane; q < p; q += 32) sA[p * NN_ + q] = vals[cnt++] * inv;
    }
    __syncthreads();

    for (int e = tid; e < NN_ * NN_; e += 256) outA[e] = sA[e];

    if (tid < 64) {
        int c = 0;
        for (int q = 0; q < 64; q++) c += (sA[tid * NN_ + q] > 1e-15f) ? 1 : 0;
        d1[tid] = rsqrtf(1.f + (float)c);
    } else if (tid < 80) {
        int p = tid;
        int c = 0;
        for (int q = 64; q < 80; q++) c += (sA[p * NN_ + q] > 1e-15f) ? 1 : 0;
        d2[tid - 64] = rsqrtf(1.f + (float)c);
    }
    __syncthreads();

    for (int e = tid; e < 64 * 64; e += 256) {
        int p = e >> 6, q = e & 63;
        g_An11[e] = d1[p] * sA[p * NN_ + q] * d1[q];
    }
    if (tid < 256) {
        int p = tid >> 4, q = tid & 15;
        g_An22[tid] = d2[p] * sA[(64 + p) * NN_ + 64 + q] * d2[q];
    }

    if (tid < 16) {
        int p = 64 + tid;
        float mx = NEGV;
        for (int i = 0; i < 64; i++) {
            float a = sA[p * NN_ + i];
            mx = fmaxf(mx, (a != 0.f) ? a : NEGV);
        }
        float sum = 0.f;
        for (int i = 0; i < 64; i++) {
            float a = sA[p * NN_ + i];
            sum += expf(((a != 0.f) ? a : NEGV) - mx);
        }
        float inv = 1.f / sum;
        unsigned int b0 = 0u, b1 = 0u;
        for (int i = 0; i < 64; i++) {
            float a = sA[p * NN_ + i];
            float v = expf(((a != 0.f) ? a : NEGV) - mx) * inv;
            if (v >= 0.004f) {
                if (i < 32) b0 |= (1u << i);
                else        b1 |= (1u << (i - 32));
            }
        }
        g_AtmBits[tid * 2]     = b0;
        g_AtmBits[tid * 2 + 1] = b1;
    }

    // theta (padded): rows >=50 zero, cols r>=50 zero
    for (int e = tid; e < 52 * 64; e += 256) {
        int c = e >> 6, r = e & 63;
        float s = 0.f;
        if (c < 50 && r < 50) {
            #pragma unroll 8
            for (int k = 0; k < 64; k++) s = fmaf(Wk[c * 64 + k], Wk[r * 64 + k], s);
        }
        g_thetaB[e] = s;
    }

    // transposed weights
    for (int e = tid; e < 52 * 64; e += 256) {
        int k = e >> 6, o = e & 63;
        g_Wg1aT[e] = (k < 51) ? Wg1a[o * 51 + k] : 0.f;
    }
    for (int e = tid; e < 51 * 64; e += 256) {
        int k = e >> 6, o = e & 63;
        g_Wg2aT[e] = Wg2a[o * 51 + k];
    }
    for (int e = tid; e < 64 * 64; e += 256) {
        int h = e >> 6, o = e & 63;
        g_Wg1bT[e] = (o < 50) ? Wg1b[o * 64 + h] : 0.f;
    }

    if (tid == 0) {
        float sg = 1.f / (1.f + expf(-smoothing[0]));
        g_coef = -0.5f / (sg * 0.01f);
    }
}

// =====================================================================
// Kernel 1: gather + 3-layer MLP. 128 tokens/block, 8x8 thread tiles.
// =====================================================================
#define PT  132   // token buffer pitch (mult of 4, >=128)
#define PW1 52    // staged w1 pitch (even)

__global__ void __launch_bounds__(256, 2) k_mlp(
    const float* __restrict__ data,
    const float* __restrict__ emb0, const float* __restrict__ emb1, const float* __restrict__ emb2,
    const float* __restrict__ w1, const float* __restrict__ b1,
    const float* __restrict__ w2, const float* __restrict__ b2,
    const float* __restrict__ w3, const float* __restrict__ b3,
    const float* __restrict__ M, const float* __restrict__ Wk,
    const float* __restrict__ smoothing,
    const float* __restrict__ Wg1a, const float* __restrict__ Wg1b,
    const float* __restrict__ Wg2a,
    float* __restrict__ outA)
{
    extern __shared__ float sh[];

    if (blockIdx.x == 640) {
        do_setup(sh, M, Wk, smoothing, Wg1a, Wg1b, Wg2a, outA);
        return;
    }

    float* T     = sh;               // 128 * PT (feature-major: [feat][token])
    float* w1s   = T + 128 * PT;     // 128 * PW1
    float* sLast = w1s + 128 * PW1;  // 128

    const int tid = threadIdx.x;
    const int cx = tid & 15, ry = tid >> 4;   // cx -> 8 tokens, ry -> rows
    const int base = blockIdx.x * 128;

    if (tid < 128) sLast[tid] = data[(size_t)(base + tid) * 6 + 5];

    for (int e = tid; e < 128 * PW1; e += 256) {
        int o = e / PW1, k = e % PW1;
        w1s[e] = (k < 51) ? w1[o * 51 + k] : 0.f;
    }
    for (int e = tid; e < 52 * 128; e += 256) {
        int c = e >> 7, t = e & 127;
        const float* dr = data + (size_t)(base + t) * 6;
        float v;
        if (c < 32)      { int i0 = (int)dr[0]; v = emb0[i0 * 32 + c]; }
        else if (c < 40) { int i1 = (int)dr[1]; v = emb1[i1 * 8 + (c - 32)]; }
        else if (c < 48) { int i2 = (int)dr[2]; v = emb2[i2 * 8 + (c - 40)]; }
        else if (c < 51) { v = dr[3 + (c - 48)]; }
        else             { v = 0.f; }
        T[c * PT + t] = v;
    }
    __syncthreads();

    // ---- GEMM1: h1[o][t] = relu(w1s @ T + b1), K=52, 8x8 tiles ----
    {
        u64 acc[8][4];
        #pragma unroll
        for (int i = 0; i < 8; i++)
            #pragma unroll
            for (int j = 0; j < 4; j++) acc[i][j] = 0ull;
        for (int k0 = 0; k0 < 52; k0 += 2) {
            float2 ap[8];
            #pragma unroll
            for (int i = 0; i < 8; i++)
                ap[i] = *reinterpret_cast<const float2*>(&w1s[(ry + 16 * i) * PW1 + k0]);
            #pragma unroll
            for (int kk = 0; kk < 2; kk++) {
                const float* tp = &T[(k0 + kk) * PT + 8 * cx];
                ulonglong2 b0 = *reinterpret_cast<const ulonglong2*>(tp);
                ulonglong2 b1v = *reinterpret_cast<const ulonglong2*>(tp + 4);
                #pragma unroll
                for (int i = 0; i < 8; i++) {
                    u64 ad = dup2(kk ? ap[i].y : ap[i].x);
                    acc[i][0] = fma2(ad, b0.x, acc[i][0]);
                    acc[i][1] = fma2(ad, b0.y, acc[i][1]);
                    acc[i][2] = fma2(ad, b1v.x, acc[i][2]);
                    acc[i][3] = fma2(ad, b1v.y, acc[i][3]);
                }
            }
        }
        __syncthreads();
        #pragma unroll
        for (int i = 0; i < 8; i++) {
            int o = ry + 16 * i;
            float bo = __ldg(&b1[o]);
            float4 v0, v1;
            up2(acc[i][0], v0.x, v0.y);
            up2(acc[i][1], v0.z, v0.w);
            up2(acc[i][2], v1.x, v1.y);
            up2(acc[i][3], v1.z, v1.w);
            v0.x = fmaxf(v0.x + bo, 0.f); v0.y = fmaxf(v0.y + bo, 0.f);
            v0.z = fmaxf(v0.z + bo, 0.f); v0.w = fmaxf(v0.w + bo, 0.f);
            v1.x = fmaxf(v1.x + bo, 0.f); v1.y = fmaxf(v1.y + bo, 0.f);
            v1.z = fmaxf(v1.z + bo, 0.f); v1.w = fmaxf(v1.w + bo, 0.f);
            *reinterpret_cast<float4*>(&T[o * PT + 8 * cx]) = v0;
            *reinterpret_cast<float4*>(&T[o * PT + 8 * cx + 4]) = v1;
        }
        __syncthreads();
    }

    // ---- GEMM2: h2 = relu(w2 @ T + b2), K=128, 8x8 tiles ----
    {
        u64 acc[8][4];
        #pragma unroll
        for (int i = 0; i < 8; i++)
            #pragma unroll
            for (int j = 0; j < 4; j++) acc[i][j] = 0ull;
        #pragma unroll 2
        for (int k0 = 0; k0 < 128; k0 += 2) {
            float2 ap[8];
            #pragma unroll
            for (int i = 0; i < 8; i++)
                ap[i] = *reinterpret_cast<const float2*>(&w2[(ry + 16 * i) * 128 + k0]);
            #pragma unroll
            for (int kk = 0; kk < 2; kk++) {
                const float* tp = &T[(k0 + kk) * PT + 8 * cx];
                ulonglong2 b0 = *reinterpret_cast<const ulonglong2*>(tp);
                ulonglong2 b1v = *reinterpret_cast<const ulonglong2*>(tp + 4);
                #pragma unroll
                for (int i = 0; i < 8; i++) {
                    u64 ad = dup2(kk ? ap[i].y : ap[i].x);
                    acc[i][0] = fma2(ad, b0.x, acc[i][0]);
                    acc[i][1] = fma2(ad, b0.y, acc[i][1]);
                    acc[i][2] = fma2(ad, b1v.x, acc[i][2]);
                    acc[i][3] = fma2(ad, b1v.y, acc[i][3]);
                }
            }
        }
        __syncthreads();
        #pragma unroll
        for (int i = 0; i < 8; i++) {
            int o = ry + 16 * i;
            float bo = __ldg(&b2[o]);
            float4 v0, v1;
            up2(acc[i][0], v0.x, v0.y);
            up2(acc[i][1], v0.z, v0.w);
            up2(acc[i][2], v1.x, v1.y);
            up2(acc[i][3], v1.z, v1.w);
            v0.x = fmaxf(v0.x + bo, 0.f); v0.y = fmaxf(v0.y + bo, 0.f);
            v0.z = fmaxf(v0.z + bo, 0.f); v0.w = fmaxf(v0.w + bo, 0.f);
            v1.x = fmaxf(v1.x + bo, 0.f); v1.y = fmaxf(v1.y + bo, 0.f);
            v1.z = fmaxf(v1.z + bo, 0.f); v1.w = fmaxf(v1.w + bo, 0.f);
            *reinterpret_cast<float4*>(&T[o * PT + 8 * cx]) = v0;
            *reinterpret_cast<float4*>(&T[o * PT + 8 * cx + 4]) = v1;
        }
        __syncthreads();
    }

    // ---- GEMM3: h3 = w3 @ T + b3 (o<50) -> g_x, K=128, 4x8 tiles ----
    {
        u64 acc[4][4];
        #pragma unroll
        for (int i = 0; i < 4; i++)
            #pragma unroll
            for (int j = 0; j < 4; j++) acc[i][j] = 0ull;
        #pragma unroll 2
        for (int k0 = 0; k0 < 128; k0 += 2) {
            float2 ap[4];
            #pragma unroll
            for (int i = 0; i < 4; i++) {
                int o = ry + 16 * i;
                ap[i] = (o < 50) ? *reinterpret_cast<const float2*>(&w3[o * 128 + k0])
                                 : make_float2(0.f, 0.f);
            }
            #pragma unroll
            for (int kk = 0; kk < 2; kk++) {
                const float* tp = &T[(k0 + kk) * PT + 8 * cx];
                ulonglong2 b0 = *reinterpret_cast<const ulonglong2*>(tp);
                ulonglong2 b1v = *reinterpret_cast<const ulonglong2*>(tp + 4);
                #pragma unroll
                for (int i = 0; i < 4; i++) {
                    u64 ad = dup2(kk ? ap[i].y : ap[i].x);
                    acc[i][0] = fma2(ad, b0.x, acc[i][0]);
                    acc[i][1] = fma2(ad, b0.y, acc[i][1]);
                    acc[i][2] = fma2(ad, b1v.x, acc[i][2]);
                    acc[i][3] = fma2(ad, b1v.y, acc[i][3]);
                }
            }
        }
        #pragma unroll
        for (int i = 0; i < 4; i++) {
            int o = ry + 16 * i;
            if (o < 50) {
                float bo = __ldg(&b3[o]);
                float vv[8];
                up2(acc[i][0], vv[0], vv[1]);
                up2(acc[i][1], vv[2], vv[3]);
                up2(acc[i][2], vv[4], vv[5]);
                up2(acc[i][3], vv[6], vv[7]);
                int t = base + 8 * cx;
                #pragma unroll
                for (int j = 0; j < 8; j++)
                    g_x[(size_t)(t + j) * CC + o] = vv[j] + bo;
            }
        }
        if (tid < 128) g_x[(size_t)(base + tid) * CC + 50] = sLast[tid];
    }
}

// =====================================================================
// Kernel 2: per-graph pipeline. Round-11 gemm chain; dist uses
// triangle symmetry + paired-k fma2 (u64 LDS.64 operands).
// =====================================================================
#define PXM 52   // xs pitch (mult of 4)
#define PZB 68   // big buffer / staging pitch (mult of 4)

__device__ __forceinline__ void stage64(float* dst, const float* __restrict__ src,
                                        int rows, int tid)
{
    for (int e = tid * 4; e < rows * 64; e += 1024) {
        float4 v = *reinterpret_cast<const float4*>(src + e);
        int k = e >> 6, o = e & 63;
        *reinterpret_cast<float4*>(dst + k * PZB + o) = v;
    }
}

__device__ __forceinline__ void gemm_SS(const float* As, int pa,
                                        const float* Bs, int K,
                                        float* Cs, bool do_relu, int rg, int cg)
{
    u64 acc[4][2];
    #pragma unroll
    for (int i = 0; i < 4; i++) { acc[i][0] = 0ull; acc[i][1] = 0ull; }
    for (int k0 = 0; k0 < K; k0 += 4) {
        float4 ap[4];
        #pragma unroll
        for (int i = 0; i < 4; i++)
            ap[i] = *reinterpret_cast<const float4*>(As + (rg + i) * pa + k0);
        #pragma unroll
        for (int kk = 0; kk < 4; kk++) {
            ulonglong2 bv = *reinterpret_cast<const ulonglong2*>(Bs + (k0 + kk) * PZB + cg);
            #pragma unroll
            for (int i = 0; i < 4; i++) {
                u64 ad = dup2(f4c(ap[i], kk));
                acc[i][0] = fma2(ad, bv.x, acc[i][0]);
                acc[i][1] = fma2(ad, bv.y, acc[i][1]);
            }
        }
    }
    __syncthreads();
    #pragma unroll
    for (int i = 0; i < 4; i++) {
        float4 v;
        up2(acc[i][0], v.x, v.y);
        up2(acc[i][1], v.z, v.w);
        if (do_relu) {
            v.x = fmaxf(v.x, 0.f); v.y = fmaxf(v.y, 0.f);
            v.z = fmaxf(v.z, 0.f); v.w = fmaxf(v.w, 0.f);
        }
        *reinterpret_cast<float4*>(&Cs[(rg + i) * PZB + cg]) = v;
    }
    __syncthreads();
}

__global__ void __launch_bounds__(256, 3) k_main(
    const float* __restrict__ Wg2b,
    float* __restrict__ dout)
{
    extern __shared__ float sh[];
    float* xs  = sh;                 // 80*PXM
    float* B1  = xs + 80 * PXM;      // 64*PZB
    float* B2  = B1 + 64 * PZB;      // 64*PZB (An11, then x1)
    float* Wst = B2 + 64 * PZB;      // 64*PZB (rotating weights)
    float* z3  = Wst + 64 * PZB;     // 16*PZB (v / z3g)
    float* yhv = z3 + 16 * PZB;      // 16
    float* z4v = yhv + 16;           // 16
    float* sqv = z4v + 16;           // 80
    float* Ls  = B1;                 // alias (u dead after q-form)
    float* t2b = B2;                 // alias (x1 dead after q-form)

    const int tid = threadIdx.x;
    const int w = tid >> 5, lane = tid & 31;
    const int rg = (w >> 1) * 16 + (lane >> 3) * 4;
    const int cg = (w & 1) * 32 + (lane & 7) * 4;
    const int tx = tid & 15, ty16 = tid >> 4;
    const int b = blockIdx.x;
    const float* gx = g_x + (size_t)b * NN_ * CC;

    for (int e = tid; e < 80 * PXM; e += 256) {
        int r = e / PXM, c = e % PXM;
        xs[e] = (c < 51) ? gx[r * 51 + c] : 0.f;
    }
    stage64(Wst, g_Wg1aT, 52, tid);
    stage64(B2, g_An11, 64, tid);
    __syncthreads();

    gemm_SS(xs, PXM, Wst, 52, B1, false, rg, cg);    // z1 -> B1
    stage64(Wst, g_Wg1bT, 64, tid);
    __syncthreads();
    gemm_SS(B2, PZB, B1, 64, B1, true, rg, cg);      // t1 in-place
    gemm_SS(B1, PZB, Wst, 64, B1, false, rg, cg);    // z2 in-place
    stage64(Wst, g_thetaB, 52, tid);
    __syncthreads();
    gemm_SS(B2, PZB, B1, 64, B2, false, rg, cg);     // x1 -> B2
    gemm_SS(B2, PZB, Wst, 52, B1, false, rg, cg);    // u  -> B1

    // v = xf @ theta -> z3
    {
        u64 acc[2] = {0ull, 0ull};
        for (int k = 0; k < 50; k += 2) {
            float2 a = *reinterpret_cast<const float2*>(&xs[(64 + ty16) * PXM + k]);
            u64 a0 = dup2(a.x), a1 = dup2(a.y);
            acc[0] = fma2(a0, *reinterpret_cast<const u64*>(&Wst[k * PZB + 2 * tx]), acc[0]);
            acc[1] = fma2(a0, *reinterpret_cast<const u64*>(&Wst[k * PZB + 2 * tx + 32]), acc[1]);
            acc[0] = fma2(a1, *reinterpret_cast<const u64*>(&Wst[(k + 1) * PZB + 2 * tx]), acc[0]);
            acc[1] = fma2(a1, *reinterpret_cast<const u64*>(&Wst[(k + 1) * PZB + 2 * tx + 32]), acc[1]);
        }
        __syncthreads();
        #pragma unroll
        for (int j = 0; j < 2; j++) {
            float v0, v1; up2(acc[j], v0, v1);
            int c = 2 * tx + 32 * j;
            z3[ty16 * PZB + c] = v0;
            z3[ty16 * PZB + c + 1] = v1;
        }
        __syncthreads();
    }

    // q-form -> masked logits Ls
    {
        float cf = g_coef;
        float acc[4] = {0.f, 0.f, 0.f, 0.f};
        for (int k = 0; k < 50; k += 2) {
            float2 xf2 = *reinterpret_cast<const float2*>(&xs[(64 + ty16) * PXM + k]);
            float2 v2  = *reinterpret_cast<const float2*>(&z3[ty16 * PZB + k]);
            #pragma unroll
            for (int j = 0; j < 4; j++) {
                int i = tx + 16 * j;
                float2 b2v = *reinterpret_cast<const float2*>(&B2[i * PZB + k]);
                float2 b1v = *reinterpret_cast<const float2*>(&B1[i * PZB + k]);
                acc[j] = fmaf(b2v.x - xf2.x, b1v.x - v2.x, acc[j]);
                acc[j] = fmaf(b2v.y - xf2.y, b1v.y - v2.y, acc[j]);
            }
        }
        unsigned int m0 = __ldg(&g_AtmBits[ty16 * 2]);
        unsigned int m1 = __ldg(&g_AtmBits[ty16 * 2 + 1]);
        __syncthreads();
        #pragma unroll
        for (int j = 0; j < 4; j++) {
            int i = tx + 16 * j;
            bool on = (i < 32) ? ((m0 >> i) & 1u) : ((m1 >> (i - 32)) & 1u);
            Ls[ty16 * PZB + i] = on ? (cf * acc[j]) : NEGV;
        }
        stage64(Wst, g_Wg2aT, 51, tid);
        __syncthreads();
    }

    // softmax over j
    if (tid < 64) {
        int i = tid;
        float m = NEGV;
        for (int j = 0; j < 16; j++) m = fmaxf(m, Ls[j * PZB + i]);
        float s = 0.f;
        for (int j = 0; j < 16; j++) {
            float e = expf(Ls[j * PZB + i] - m);
            Ls[j * PZB + i] = e;
            s += e;
        }
        float inv = 1.f / s;
        for (int j = 0; j < 16; j++) Ls[j * PZB + i] *= inv;
    }
    __syncthreads();

    if (tid < 16) {
        float s = 0.f;
        for (int i = 0; i < 64; i++) s = fmaf(Ls[tid * PZB + i], xs[i * PXM + 50], s);
        yhv[tid] = s;
    }
    __syncthreads();
    if (tid < 16) xs[(64 + tid) * PXM + 50] = yhv[tid];
    __syncthreads();

    // gcnn2: z3g = x2 @ Wg2a^T
    {
        u64 acc[2] = {0ull, 0ull};
        for (int k = 0; k < 50; k += 2) {
            float2 a = *reinterpret_cast<const float2*>(&xs[(64 + ty16) * PXM + k]);
            u64 a0 = dup2(a.x), a1 = dup2(a.y);
            acc[0] = fma2(a0, *reinterpret_cast<const u64*>(&Wst[k * PZB + 2 * tx]), acc[0]);
            acc[1] = fma2(a0, *reinterpret_cast<const u64*>(&Wst[k * PZB + 2 * tx + 32]), acc[1]);
            acc[0] = fma2(a1, *reinterpret_cast<const u64*>(&Wst[(k + 1) * PZB + 2 * tx]), acc[0]);
            acc[1] = fma2(a1, *reinterpret_cast<const u64*>(&Wst[(k + 1) * PZB + 2 * tx + 32]), acc[1]);
        }
        {
            u64 a0 = dup2(xs[(64 + ty16) * PXM + 50]);
            acc[0] = fma2(a0, *reinterpret_cast<const u64*>(&Wst[50 * PZB + 2 * tx]), acc[0]);
            acc[1] = fma2(a0, *reinterpret_cast<const u64*>(&Wst[50 * PZB + 2 * tx + 32]), acc[1]);
        }
        __syncthreads();
        #pragma unroll
        for (int j = 0; j < 2; j++) {
            float v0, v1; up2(acc[j], v0, v1);
            int c = 2 * tx + 32 * j;
            z3[ty16 * PZB + c] = v0;
            z3[ty16 * PZB + c + 1] = v1;
        }
        __syncthreads();
    }
    // t2 = relu(An22 @ z3g)
    {
        u64 acc[2] = {0ull, 0ull};
        for (int q = 0; q < 16; q++) {
            u64 ad = dup2(__ldg(&g_An22[ty16 * 16 + q]));
            acc[0] = fma2(ad, *reinterpret_cast<const u64*>(&z3[q * PZB + 2 * tx]), acc[0]);
            acc[1] = fma2(ad, *reinterpret_cast<const u64*>(&z3[q * PZB + 2 * tx + 32]), acc[1]);
        }
        __syncthreads();
        #pragma unroll
        for (int j = 0; j < 2; j++) {
            float v0, v1; up2(acc[j], v0, v1);
            int c = 2 * tx + 32 * j;
            t2b[ty16 * PZB + c]     = fmaxf(v0, 0.f);
            t2b[ty16 * PZB + c + 1] = fmaxf(v1, 0.f);
        }
        __syncthreads();
    }
    if (tid < 16) {
        float s = 0.f;
        for (int c = 0; c < 64; c++) s = fmaf(t2b[tid * PZB + c], __ldg(&Wg2b[c]), s);
        z4v[tid] = s;
    }
    __syncthreads();
    if (tid < 16) {
        float s = 0.f;
        for (int q = 0; q < 16; q++) s = fmaf(__ldg(&g_An22[tid * 16 + q]), z4v[q], s);
        dout[b * 16 + tid] = s;
    }

    // -------- pairwise dist: symmetric, 136 upper-triangle 5x5 tiles,
    //          paired-k fma2 with direct u64 smem loads --------
    if (tid < 80) {
        float s = 0.f;
        for (int c = 0; c < 51; c++) {
            float v = xs[tid * PXM + c];
            s = fmaf(v, v, s);
        }
        sqv[tid] = s;
    }
    __syncthreads();
    if (tid < 136) {
        // tid = J*(J+1)/2 + I with 0 <= I <= J <= 15
        int J = (int)((sqrtf(8.f * (float)tid + 1.f) - 1.f) * 0.5f);
        while ((J + 1) * (J + 2) / 2 <= tid) J++;
        while (J * (J + 1) / 2 > tid) J--;
        int I = tid - J * (J + 1) / 2;

        u64 acc[5][5];
        #pragma unroll
        for (int i = 0; i < 5; i++)
            #pragma unroll
            for (int j = 0; j < 5; j++) acc[i][j] = 0ull;
        for (int k0 = 0; k0 < 52; k0 += 2) {
            u64 a2[5], b2[5];
            #pragma unroll
            for (int i = 0; i < 5; i++)
                a2[i] = *reinterpret_cast<const u64*>(&xs[(I * 5 + i) * PXM + k0]);
            #pragma unroll
            for (int j = 0; j < 5; j++)
                b2[j] = *reinterpret_cast<const u64*>(&xs[(J * 5 + j) * PXM + k0]);
            #pragma unroll
            for (int i = 0; i < 5; i++)
                #pragma unroll
                for (int j = 0; j < 5; j++)
                    acc[i][j] = fma2(a2[i], b2[j], acc[i][j]);
        }
        float* dd = dout + DIST_OFF + (size_t)b * 6400;
        #pragma unroll
        for (int i = 0; i < 5; i++)
            #pragma unroll
            for (int j = 0; j < 5; j++) {
                int n = I * 5 + i, m = J * 5 + j;
                float lo, hi; up2(acc[i][j], lo, hi);
                float s = lo + hi;
                float d2 = sqv[n] + sqv[m] - 2.f * s;
                float dv = (d2 > 0.f) ? sqrtf(d2) : 0.f;
                dd[n * 80 + m] = dv;
                dd[m * 80 + n] = dv;
            }
    }
}

// =====================================================================
// launcher
// =====================================================================
extern "C" void kernel_launch(void* const* d_in, const int* in_sizes, int n_in,
                              void* d_out, int out_size)
{
    const float* data  = (const float*)d_in[0];
    const float* emb0  = (const float*)d_in[1];
    const float* emb1  = (const float*)d_in[2];
    const float* emb2  = (const float*)d_in[3];
    const float* w1    = (const float*)d_in[4];
    const float* b1    = (const float*)d_in[5];
    const float* w2    = (const float*)d_in[6];
    const float* b2    = (const float*)d_in[7];
    const float* w3    = (const float*)d_in[8];
    const float* b3    = (const float*)d_in[9];
    const float* M     = (const float*)d_in[10];
    const float* Wg1a  = (const float*)d_in[11];
    const float* Wg1b  = (const float*)d_in[12];
    const float* Wk    = (const float*)d_in[13];
    const float* smoothing = (const float*)d_in[14];
    const float* Wg2a  = (const float*)d_in[15];
    const float* Wg2b  = (const float*)d_in[16];
    float* out = (float*)d_out;

    const int SMEM_MLP  = (128 * PT + 128 * PW1 + 128) * 4;
    const int SMEM_MAIN = (80 * PXM + 3 * 64 * PZB + 16 * PZB + 16 + 16 + 80) * 4;

    cudaFuncSetAttribute(k_mlp, cudaFuncAttributeMaxDynamicSharedMemorySize, SMEM_MLP);
    cudaFuncSetAttribute(k_main, cudaFuncAttributeMaxDynamicSharedMemorySize, SMEM_MAIN);

    k_mlp<<<641, 256, SMEM_MLP>>>(data, emb0, emb1, emb2, w1, b1, w2, b2, w3, b3,
                                  M, Wk, smoothing, Wg1a, Wg1b, Wg2a, out + A_OFF);
    k_main<<<1024, 256, SMEM_MAIN>>>(Wg2b, out);
}

// round 15
// speedup vs baseline: 1.0301x; 1.0301x over previous
#include <cuda_runtime.h>
#include <math.h>

// ---------------- problem constants ----------------
#define NN_   80
#define CC    51
#define DM_   26
#define NEGV  -1e30f

#define DIST_OFF 16384
#define A_OFF    (16384 + 1024*6400)

typedef unsigned long long u64;

// ---------------- f32x2 packed helpers ----------------
__device__ __forceinline__ u64 pk2(float lo, float hi) {
    u64 r; asm("mov.b64 %0,{%1,%2};" : "=l"(r) : "f"(lo), "f"(hi)); return r;
}
__device__ __forceinline__ u64 dup2(float v) { return pk2(v, v); }
__device__ __forceinline__ void up2(u64 v, float& a, float& b) {
    asm("mov.b64 {%0,%1},%2;" : "=f"(a), "=f"(b) : "l"(v));
}
__device__ __forceinline__ u64 fma2(u64 a, u64 b, u64 c) {
    u64 d; asm("fma.rn.f32x2 %0,%1,%2,%3;" : "=l"(d) : "l"(a), "l"(b), "l"(c)); return d;
}
__device__ __forceinline__ float f4c(const float4& v, int kk) {
    return (kk == 0) ? v.x : (kk == 1) ? v.y : (kk == 2) ? v.z : v.w;
}

// ---------------- device constants (written by setup block) ----------------
__device__ float g_An11[64 * 64];
__device__ float g_An22[16 * 16];
__device__ unsigned int g_AtmBits[32];
__device__ float g_Wg1aT[52 * 64];   // [k][o], row 51 zero
__device__ float g_Wg2aT[51 * 64];   // [k][o]
__device__ float g_Wg1bT[64 * 64];   // [h][o2], o2>=50 zero
__device__ float g_thetaB[52 * 64];  // [c][r], r>=50 zero, rows 50,51 zero
__device__ float g_coef;
__device__ int   g_ready;            // zero-initialized

// =====================================================================
// setup (block 0 of fused kernel, 256 threads)
// =====================================================================
__device__ void do_setup(float* sh,
                         const float* __restrict__ M, const float* __restrict__ Wk,
                         const float* __restrict__ smoothing,
                         const float* __restrict__ Wg1a, const float* __restrict__ Wg1b,
                         const float* __restrict__ Wg2a,
                         float* __restrict__ outA)
{
    float* sM = sh;                 // 80*26
    float* sA = sM + NN_ * DM_;     // 80*80
    float* d1 = sA + NN_ * NN_;     // 64
    float* d2 = d1 + 64;            // 16
    const int tid = threadIdx.x;
    const int lane = tid & 31, warp = tid >> 5;

    for (int e = tid; e < NN_ * DM_; e += 256) sM[e] = M[e];
    for (int e = tid; e < NN_ * NN_; e += 256) sA[e] = 0.f;
    __syncthreads();

    for (int p = warp; p < NN_; p += 8) {
        float vals[3];
        float mx = NEGV;
        int cnt = 0;
        for (int q = lane; q < p; q += 32) {
            float s = 0.f;
            #pragma unroll
            for (int k = 0; k < DM_; k++) s = fmaf(sM[p * DM_ + k], sM[q * DM_ + k], s);
            s = fmaxf(s, 0.f);
            vals[cnt++] = s;
            mx = fmaxf(mx, s);
        }
        #pragma unroll
        for (int off = 16; off; off >>= 1) mx = fmaxf(mx, __shfl_xor_sync(0xffffffffu, mx, off));
        float sum = 0.f;
        for (int c = 0; c < cnt; c++) { vals[c] = expf(vals[c] - mx); sum += vals[c]; }
        #pragma unroll
        for (int off = 16; off; off >>= 1) sum += __shfl_xor_sync(0xffffffffu, sum, off);
        float inv = (p > 0) ? 1.f / sum : 0.f;
        cnt = 0;
        for (int q = lane; q < p; q += 32) sA[p * NN_ + q] = vals[cnt++] * inv;
    }
    __syncthreads();

    for (int e = tid; e < NN_ * NN_; e += 256) outA[e] = sA[e];

    if (tid < 64) {
        int c = 0;
        for (int q = 0; q < 64; q++) c += (sA[tid * NN_ + q] > 1e-15f) ? 1 : 0;
        d1[tid] = rsqrtf(1.f + (float)c);
    } else if (tid < 80) {
        int p = tid;
        int c = 0;
        for (int q = 64; q < 80; q++) c += (sA[p * NN_ + q] > 1e-15f) ? 1 : 0;
        d2[tid - 64] = rsqrtf(1.f + (float)c);
    }
    __syncthreads();

    for (int e = tid; e < 64 * 64; e += 256) {
        int p = e >> 6, q = e & 63;
        g_An11[e] = d1[p] * sA[p * NN_ + q] * d1[q];
    }
    if (tid < 256) {
        int p = tid >> 4, q = tid & 15;
        g_An22[tid] = d2[p] * sA[(64 + p) * NN_ + 64 + q] * d2[q];
    }

    if (tid < 16) {
        int p = 64 + tid;
        float mx = NEGV;
        for (int i = 0; i < 64; i++) {
            float a = sA[p * NN_ + i];
            mx = fmaxf(mx, (a != 0.f) ? a : NEGV);
        }
        float sum = 0.f;
        for (int i = 0; i < 64; i++) {
            float a = sA[p * NN_ + i];
            sum += expf(((a != 0.f) ? a : NEGV) - mx);
        }
        float inv = 1.f / sum;
        unsigned int b0 = 0u, b1 = 0u;
        for (int i = 0; i < 64; i++) {
            float a = sA[p * NN_ + i];
            float v = expf(((a != 0.f) ? a : NEGV) - mx) * inv;
            if (v >= 0.004f) {
                if (i < 32) b0 |= (1u << i);
                else        b1 |= (1u << (i - 32));
            }
        }
        g_AtmBits[tid * 2]     = b0;
        g_AtmBits[tid * 2 + 1] = b1;
    }

    for (int e = tid; e < 52 * 64; e += 256) {
        int c = e >> 6, r = e & 63;
        float s = 0.f;
        if (c < 50 && r < 50) {
            #pragma unroll 8
            for (int k = 0; k < 64; k++) s = fmaf(Wk[c * 64 + k], Wk[r * 64 + k], s);
        }
        g_thetaB[e] = s;
    }
    for (int e = tid; e < 52 * 64; e += 256) {
        int k = e >> 6, o = e & 63;
        g_Wg1aT[e] = (k < 51) ? Wg1a[o * 51 + k] : 0.f;
    }
    for (int e = tid; e < 51 * 64; e += 256) {
        int k = e >> 6, o = e & 63;
        g_Wg2aT[e] = Wg2a[o * 51 + k];
    }
    for (int e = tid; e < 64 * 64; e += 256) {
        int h = e >> 6, o = e & 63;
        g_Wg1bT[e] = (o < 50) ? Wg1b[o * 64 + h] : 0.f;
    }
    if (tid == 0) {
        float sg = 1.f / (1.f + expf(-smoothing[0]));
        g_coef = -0.5f / (sg * 0.01f);
    }
}

// =====================================================================
// Fused kernel: block 0 = setup; blocks 1..1024 = one graph each.
// smem: R(13056f: T-buffer / B1|B2|Wst) + xs(4160) + z3(1088) + small.
// =====================================================================
#define PTK 84   // MLP token buffer pitch (mult of 4)
#define PZB 68   // graph buffer pitch
#define PXM 52   // xs pitch

__device__ __forceinline__ void stage64(float* dst, const float* __restrict__ src,
                                        int rows, int tid)
{
    for (int e = tid * 4; e < rows * 64; e += 1024) {
        float4 v = *reinterpret_cast<const float4*>(src + e);
        int k = e >> 6, o = e & 63;
        *reinterpret_cast<float4*>(dst + k * PZB + o) = v;
    }
}

__device__ __forceinline__ void gemm_SS(const float* As, int pa,
                                        const float* Bs, int K,
                                        float* Cs, bool do_relu, int rg, int cg)
{
    u64 acc[4][2];
    #pragma unroll
    for (int i = 0; i < 4; i++) { acc[i][0] = 0ull; acc[i][1] = 0ull; }
    for (int k0 = 0; k0 < K; k0 += 4) {
        float4 ap[4];
        #pragma unroll
        for (int i = 0; i < 4; i++)
            ap[i] = *reinterpret_cast<const float4*>(As + (rg + i) * pa + k0);
        #pragma unroll
        for (int kk = 0; kk < 4; kk++) {
            ulonglong2 bv = *reinterpret_cast<const ulonglong2*>(Bs + (k0 + kk) * PZB + cg);
            #pragma unroll
            for (int i = 0; i < 4; i++) {
                u64 ad = dup2(f4c(ap[i], kk));
                acc[i][0] = fma2(ad, bv.x, acc[i][0]);
                acc[i][1] = fma2(ad, bv.y, acc[i][1]);
            }
        }
    }
    __syncthreads();
    #pragma unroll
    for (int i = 0; i < 4; i++) {
        float4 v;
        up2(acc[i][0], v.x, v.y);
        up2(acc[i][1], v.z, v.w);
        if (do_relu) {
            v.x = fmaxf(v.x, 0.f); v.y = fmaxf(v.y, 0.f);
            v.z = fmaxf(v.z, 0.f); v.w = fmaxf(v.w, 0.f);
        }
        *reinterpret_cast<float4*>(&Cs[(rg + i) * PZB + cg]) = v;
    }
    __syncthreads();
}

__global__ void __launch_bounds__(256, 3) k_fused(
    const float* __restrict__ data,
    const float* __restrict__ emb0, const float* __restrict__ emb1, const float* __restrict__ emb2,
    const float* __restrict__ w1, const float* __restrict__ b1,
    const float* __restrict__ w2, const float* __restrict__ b2,
    const float* __restrict__ w3, const float* __restrict__ b3,
    const float* __restrict__ M, const float* __restrict__ Wk,
    const float* __restrict__ smoothing,
    const float* __restrict__ Wg1a, const float* __restrict__ Wg1b,
    const float* __restrict__ Wg2a, const float* __restrict__ Wg2b,
    float* __restrict__ dout)
{
    extern __shared__ float sh[];
    const int tid = threadIdx.x;

    if (blockIdx.x == 0) {
        do_setup(sh, M, Wk, smoothing, Wg1a, Wg1b, Wg2a, dout + A_OFF);
        __syncthreads();
        __threadfence();
        if (tid == 0) atomicExch(&g_ready, 1);
        return;
    }

    // ---- smem layout ----
    float* R   = sh;               // 13056 floats
    float* xs  = sh + 13056;       // 80*52
    float* z3  = xs + 80 * PXM;    // 16*68 (also 'last' stash during MLP)
    float* yhv = z3 + 16 * PZB;    // 16
    float* z4v = yhv + 16;         // 16
    float* sqv = z4v + 16;         // 80
    float* T   = R;                // MLP buffer 128*84 (aliases B1|B2|part Wst)
    float* B1  = R;
    float* B2  = R + 64 * PZB;
    float* Wst = R + 2 * 64 * PZB;
    float* Ls  = B1;
    float* t2b = B2;

    const int gid = blockIdx.x - 1;

    // =========== MLP phase (feature-major, 80 tokens) ===========
    const int ryM = tid >> 3;          // 0..31
    const int cxM = tid & 7;           // 0..7 -> cols 10*cxM .. +9

    // gather X^T rows 0..50; stash last col in z3[0..79]
    for (int e = tid; e < 51 * 80; e += 256) {
        int c = e / 80, t = e - (e / 80) * 80;
        const float* dr = data + (size_t)(gid * 80 + t) * 6;
        float v;
        if (c < 32)      { int i0 = (int)dr[0]; v = emb0[i0 * 32 + c]; }
        else if (c < 40) { int i1 = (int)dr[1]; v = emb1[i1 * 8 + (c - 32)]; }
        else if (c < 48) { int i2 = (int)dr[2]; v = emb2[i2 * 8 + (c - 40)]; }
        else             { v = dr[3 + (c - 48)]; }
        T[c * PTK + t] = v;
    }
    if (tid < 80) z3[tid] = data[(size_t)(gid * 80 + tid) * 6 + 5];
    __syncthreads();

    // ---- GEMM1: h1[o][t] = relu(w1 @ X^T + b1), K=51 (scalar A: w1 pitch 51) ----
    {
        u64 acc[4][5];
        #pragma unroll
        for (int i = 0; i < 4; i++)
            #pragma unroll
            for (int j = 0; j < 5; j++) acc[i][j] = 0ull;
        int k = 0;
        for (; k + 1 < 51; k += 2) {
            float a0[4], a1[4];
            #pragma unroll
            for (int i = 0; i < 4; i++) {
                const float* wr = &w1[(ryM + 32 * i) * 51 + k];
                a0[i] = __ldg(wr); a1[i] = __ldg(wr + 1);
            }
            {
                const float* bp = &T[k * PTK + 10 * cxM];
                u64 b[5];
                #pragma unroll
                for (int j = 0; j < 5; j++) b[j] = *reinterpret_cast<const u64*>(bp + 2 * j);
                #pragma unroll
                for (int i = 0; i < 4; i++) {
                    u64 ad = dup2(a0[i]);
                    #pragma unroll
                    for (int j = 0; j < 5; j++) acc[i][j] = fma2(ad, b[j], acc[i][j]);
                }
            }
            {
                const float* bp = &T[(k + 1) * PTK + 10 * cxM];
                u64 b[5];
                #pragma unroll
                for (int j = 0; j < 5; j++) b[j] = *reinterpret_cast<const u64*>(bp + 2 * j);
                #pragma unroll
                for (int i = 0; i < 4; i++) {
                    u64 ad = dup2(a1[i]);
                    #pragma unroll
                    for (int j = 0; j < 5; j++) acc[i][j] = fma2(ad, b[j], acc[i][j]);
                }
            }
        }
        { // k = 50
            const float* bp = &T[50 * PTK + 10 * cxM];
            u64 b[5];
            #pragma unroll
            for (int j = 0; j < 5; j++) b[j] = *reinterpret_cast<const u64*>(bp + 2 * j);
            #pragma unroll
            for (int i = 0; i < 4; i++) {
                u64 ad = dup2(__ldg(&w1[(ryM + 32 * i) * 51 + 50]));
                #pragma unroll
                for (int j = 0; j < 5; j++) acc[i][j] = fma2(ad, b[j], acc[i][j]);
            }
        }
        __syncthreads();
        #pragma unroll
        for (int i = 0; i < 4; i++) {
            int o = ryM + 32 * i;
            float bo = __ldg(&b1[o]);
            #pragma unroll
            for (int j = 0; j < 5; j++) {
                float v0, v1; up2(acc[i][j], v0, v1);
                v0 = fmaxf(v0 + bo, 0.f); v1 = fmaxf(v1 + bo, 0.f);
                *reinterpret_cast<u64*>(&T[o * PTK + 10 * cxM + 2 * j]) = pk2(v0, v1);
            }
        }
        __syncthreads();
    }

    // ---- GEMM2: h2 = relu(w2 @ h1 + b2), K=128 (A float2, in-place) ----
    {
        u64 acc[4][5];
        #pragma unroll
        for (int i = 0; i < 4; i++)
            #pragma unroll
            for (int j = 0; j < 5; j++) acc[i][j] = 0ull;
        #pragma unroll 2
        for (int k = 0; k < 128; k += 2) {
            float2 ap[4];
            #pragma unroll
            for (int i = 0; i < 4; i++)
                ap[i] = *reinterpret_cast<const float2*>(&w2[(ryM + 32 * i) * 128 + k]);
            {
                const float* bp = &T[k * PTK + 10 * cxM];
                u64 b[5];
                #pragma unroll
                for (int j = 0; j < 5; j++) b[j] = *reinterpret_cast<const u64*>(bp + 2 * j);
                #pragma unroll
                for (int i = 0; i < 4; i++) {
                    u64 ad = dup2(ap[i].x);
                    #pragma unroll
                    for (int j = 0; j < 5; j++) acc[i][j] = fma2(ad, b[j], acc[i][j]);
                }
            }
            {
                const float* bp = &T[(k + 1) * PTK + 10 * cxM];
                u64 b[5];
                #pragma unroll
                for (int j = 0; j < 5; j++) b[j] = *reinterpret_cast<const u64*>(bp + 2 * j);
                #pragma unroll
                for (int i = 0; i < 4; i++) {
                    u64 ad = dup2(ap[i].y);
                    #pragma unroll
                    for (int j = 0; j < 5; j++) acc[i][j] = fma2(ad, b[j], acc[i][j]);
                }
            }
        }
        __syncthreads();
        #pragma unroll
        for (int i = 0; i < 4; i++) {
            int o = ryM + 32 * i;
            float bo = __ldg(&b2[o]);
            #pragma unroll
            for (int j = 0; j < 5; j++) {
                float v0, v1; up2(acc[i][j], v0, v1);
                v0 = fmaxf(v0 + bo, 0.f); v1 = fmaxf(v1 + bo, 0.f);
                *reinterpret_cast<u64*>(&T[o * PTK + 10 * cxM + 2 * j]) = pk2(v0, v1);
            }
        }
        __syncthreads();
    }

    // ---- GEMM3: h3 = w3 @ h2 + b3 (o<50) -> xs (transposed scatter), K=128 ----
    {
        u64 acc[2][5];
        #pragma unroll
        for (int i = 0; i < 2; i++)
            #pragma unroll
            for (int j = 0; j < 5; j++) acc[i][j] = 0ull;
        #pragma unroll 2
        for (int k = 0; k < 128; k += 2) {
            float2 ap[2];
            #pragma unroll
            for (int i = 0; i < 2; i++) {
                int o = ryM + 32 * i;
                ap[i] = (o < 50) ? *reinterpret_cast<const float2*>(&w3[o * 128 + k])
                                 : make_float2(0.f, 0.f);
            }
            {
                const float* bp = &T[k * PTK + 10 * cxM];
                u64 b[5];
                #pragma unroll
                for (int j = 0; j < 5; j++) b[j] = *reinterpret_cast<const u64*>(bp + 2 * j);
                #pragma unroll
                for (int i = 0; i < 2; i++) {
                    u64 ad = dup2(ap[i].x);
                    #pragma unroll
                    for (int j = 0; j < 5; j++) acc[i][j] = fma2(ad, b[j], acc[i][j]);
                }
            }
            {
                const float* bp = &T[(k + 1) * PTK + 10 * cxM];
                u64 b[5];
                #pragma unroll
                for (int j = 0; j < 5; j++) b[j] = *reinterpret_cast<const u64*>(bp + 2 * j);
                #pragma unroll
                for (int i = 0; i < 2; i++) {
                    u64 ad = dup2(ap[i].y);
                    #pragma unroll
                    for (int j = 0; j < 5; j++) acc[i][j] = fma2(ad, b[j], acc[i][j]);
                }
            }
        }
        // scatter into xs (token-major); no alias with T
        #pragma unroll
        for (int i = 0; i < 2; i++) {
            int o = ryM + 32 * i;
            if (o < 50) {
                float bo = __ldg(&b3[o]);
                #pragma unroll
                for (int j = 0; j < 5; j++) {
                    float v0, v1; up2(acc[i][j], v0, v1);
                    int t = 10 * cxM + 2 * j;
                    xs[t * PXM + o]       = v0 + bo;
                    xs[(t + 1) * PXM + o] = v1 + bo;
                }
            }
        }
        if (tid < 80) {
            xs[tid * PXM + 50] = z3[tid];
            xs[tid * PXM + 51] = 0.f;
        }
    }

    // ---- wait for setup constants (block 0 finishes during MLP phase) ----
    if (tid == 0) { while (atomicAdd(&g_ready, 0) == 0) { } }
    __syncthreads();

    // =========== graph phase (round-14 k_main body) ===========
    const int w = tid >> 5, lane = tid & 31;
    const int rg = (w >> 1) * 16 + (lane >> 3) * 4;
    const int cg = (w & 1) * 32 + (lane & 7) * 4;
    const int tx = tid & 15, ty16 = tid >> 4;

    stage64(Wst, g_Wg1aT, 52, tid);
    stage64(B2, g_An11, 64, tid);
    __syncthreads();

    gemm_SS(xs, PXM, Wst, 52, B1, false, rg, cg);    // z1 -> B1
    stage64(Wst, g_Wg1bT, 64, tid);
    __syncthreads();
    gemm_SS(B2, PZB, B1, 64, B1, true, rg, cg);      // t1 in-place
    gemm_SS(B1, PZB, Wst, 64, B1, false, rg, cg);    // z2 in-place
    stage64(Wst, g_thetaB, 52, tid);
    __syncthreads();
    gemm_SS(B2, PZB, B1, 64, B2, false, rg, cg);     // x1 -> B2
    gemm_SS(B2, PZB, Wst, 52, B1, false, rg, cg);    // u  -> B1

    // v = xf @ theta -> z3
    {
        u64 acc[2] = {0ull, 0ull};
        for (int k = 0; k < 50; k += 2) {
            float2 a = *reinterpret_cast<const float2*>(&xs[(64 + ty16) * PXM + k]);
            u64 a0 = dup2(a.x), a1 = dup2(a.y);
            acc[0] = fma2(a0, *reinterpret_cast<const u64*>(&Wst[k * PZB + 2 * tx]), acc[0]);
            acc[1] = fma2(a0, *reinterpret_cast<const u64*>(&Wst[k * PZB + 2 * tx + 32]), acc[1]);
            acc[0] = fma2(a1, *reinterpret_cast<const u64*>(&Wst[(k + 1) * PZB + 2 * tx]), acc[0]);
            acc[1] = fma2(a1, *reinterpret_cast<const u64*>(&Wst[(k + 1) * PZB + 2 * tx + 32]), acc[1]);
        }
        __syncthreads();
        #pragma unroll
        for (int j = 0; j < 2; j++) {
            float v0, v1; up2(acc[j], v0, v1);
            int c = 2 * tx + 32 * j;
            z3[ty16 * PZB + c] = v0;
            z3[ty16 * PZB + c + 1] = v1;
        }
        __syncthreads();
    }

    // q-form -> masked logits Ls
    {
        float cf = g_coef;
        float acc[4] = {0.f, 0.f, 0.f, 0.f};
        for (int k = 0; k < 50; k += 2) {
            float2 xf2 = *reinterpret_cast<const float2*>(&xs[(64 + ty16) * PXM + k]);
            float2 v2  = *reinterpret_cast<const float2*>(&z3[ty16 * PZB + k]);
            #pragma unroll
            for (int j = 0; j < 4; j++) {
                int i = tx + 16 * j;
                float2 b2v = *reinterpret_cast<const float2*>(&B2[i * PZB + k]);
                float2 b1v = *reinterpret_cast<const float2*>(&B1[i * PZB + k]);
                acc[j] = fmaf(b2v.x - xf2.x, b1v.x - v2.x, acc[j]);
                acc[j] = fmaf(b2v.y - xf2.y, b1v.y - v2.y, acc[j]);
            }
        }
        unsigned int m0 = __ldg(&g_AtmBits[ty16 * 2]);
        unsigned int m1 = __ldg(&g_AtmBits[ty16 * 2 + 1]);
        __syncthreads();
        #pragma unroll
        for (int j = 0; j < 4; j++) {
            int i = tx + 16 * j;
            bool on = (i < 32) ? ((m0 >> i) & 1u) : ((m1 >> (i - 32)) & 1u);
            Ls[ty16 * PZB + i] = on ? (cf * acc[j]) : NEGV;
        }
        stage64(Wst, g_Wg2aT, 51, tid);
        __syncthreads();
    }

    // softmax over j
    if (tid < 64) {
        int i = tid;
        float m = NEGV;
        for (int j = 0; j < 16; j++) m = fmaxf(m, Ls[j * PZB + i]);
        float s = 0.f;
        for (int j = 0; j < 16; j++) {
            float e = expf(Ls[j * PZB + i] - m);
            Ls[j * PZB + i] = e;
            s += e;
        }
        float inv = 1.f / s;
        for (int j = 0; j < 16; j++) Ls[j * PZB + i] *= inv;
    }
    __syncthreads();

    if (tid < 16) {
        float s = 0.f;
        for (int i = 0; i < 64; i++) s = fmaf(Ls[tid * PZB + i], xs[i * PXM + 50], s);
        yhv[tid] = s;
    }
    __syncthreads();
    if (tid < 16) xs[(64 + tid) * PXM + 50] = yhv[tid];
    __syncthreads();

    // gcnn2: z3g = x2 @ Wg2a^T
    {
        u64 acc[2] = {0ull, 0ull};
        for (int k = 0; k < 50; k += 2) {
            float2 a = *reinterpret_cast<const float2*>(&xs[(64 + ty16) * PXM + k]);
            u64 a0 = dup2(a.x), a1 = dup2(a.y);
            acc[0] = fma2(a0, *reinterpret_cast<const u64*>(&Wst[k * PZB + 2 * tx]), acc[0]);
            acc[1] = fma2(a0, *reinterpret_cast<const u64*>(&Wst[k * PZB + 2 * tx + 32]), acc[1]);
            acc[0] = fma2(a1, *reinterpret_cast<const u64*>(&Wst[(k + 1) * PZB + 2 * tx]), acc[0]);
            acc[1] = fma2(a1, *reinterpret_cast<const u64*>(&Wst[(k + 1) * PZB + 2 * tx + 32]), acc[1]);
        }
        {
            u64 a0 = dup2(xs[(64 + ty16) * PXM + 50]);
            acc[0] = fma2(a0, *reinterpret_cast<const u64*>(&Wst[50 * PZB + 2 * tx]), acc[0]);
            acc[1] = fma2(a0, *reinterpret_cast<const u64*>(&Wst[50 * PZB + 2 * tx + 32]), acc[1]);
        }
        __syncthreads();
        #pragma unroll
        for (int j = 0; j < 2; j++) {
            float v0, v1; up2(acc[j], v0, v1);
            int c = 2 * tx + 32 * j;
            z3[ty16 * PZB + c] = v0;
            z3[ty16 * PZB + c + 1] = v1;
        }
        __syncthreads();
    }
    // t2 = relu(An22 @ z3g)
    {
        u64 acc[2] = {0ull, 0ull};
        for (int q = 0; q < 16; q++) {
            u64 ad = dup2(__ldg(&g_An22[ty16 * 16 + q]));
            acc[0] = fma2(ad, *reinterpret_cast<const u64*>(&z3[q * PZB + 2 * tx]), acc[0]);
            acc[1] = fma2(ad, *reinterpret_cast<const u64*>(&z3[q * PZB + 2 * tx + 32]), acc[1]);
        }
        __syncthreads();
        #pragma unroll
        for (int j = 0; j < 2; j++) {
            float v0, v1; up2(acc[j], v0, v1);
            int c = 2 * tx + 32 * j;
            t2b[ty16 * PZB + c]     = fmaxf(v0, 0.f);
            t2b[ty16 * PZB + c + 1] = fmaxf(v1, 0.f);
        }
        __syncthreads();
    }
    if (tid < 16) {
        float s = 0.f;
        for (int c = 0; c < 64; c++) s = fmaf(t2b[tid * PZB + c], __ldg(&Wg2b[c]), s);
        z4v[tid] = s;
    }
    __syncthreads();
    if (tid < 16) {
        float s = 0.f;
        for (int q = 0; q < 16; q++) s = fmaf(__ldg(&g_An22[tid * 16 + q]), z4v[q], s);
        dout[gid * 16 + tid] = s;
    }

    // pairwise dist (symmetric triangle, fma2)
    if (tid < 80) {
        float s = 0.f;
        for (int c = 0; c < 51; c++) {
            float v = xs[tid * PXM + c];
            s = fmaf(v, v, s);
        }
        sqv[tid] = s;
    }
    __syncthreads();
    if (tid < 136) {
        int J = (int)((sqrtf(8.f * (float)tid + 1.f) - 1.f) * 0.5f);
        while ((J + 1) * (J + 2) / 2 <= tid) J++;
        while (J * (J + 1) / 2 > tid) J--;
        int I = tid - J * (J + 1) / 2;

        u64 acc[5][5];
        #pragma unroll
        for (int i = 0; i < 5; i++)
            #pragma unroll
            for (int j = 0; j < 5; j++) acc[i][j] = 0ull;
        for (int k0 = 0; k0 < 52; k0 += 2) {
            u64 a2[5], b2v[5];
            #pragma unroll
            for (int i = 0; i < 5; i++)
                a2[i] = *reinterpret_cast<const u64*>(&xs[(I * 5 + i) * PXM + k0]);
            #pragma unroll
            for (int j = 0; j < 5; j++)
                b2v[j] = *reinterpret_cast<const u64*>(&xs[(J * 5 + j) * PXM + k0]);
            #pragma unroll
            for (int i = 0; i < 5; i++)
                #pragma unroll
                for (int j = 0; j < 5; j++)
                    acc[i][j] = fma2(a2[i], b2v[j], acc[i][j]);
        }
        float* dd = dout + DIST_OFF + (size_t)gid * 6400;
        #pragma unroll
        for (int i = 0; i < 5; i++)
            #pragma unroll
            for (int j = 0; j < 5; j++) {
                int n = I * 5 + i, m = J * 5 + j;
                float lo, hi; up2(acc[i][j], lo, hi);
                float s = lo + hi;
                float d2 = sqv[n] + sqv[m] - 2.f * s;
                float dv = (d2 > 0.f) ? sqrtf(d2) : 0.f;
                dd[n * 80 + m] = dv;
                dd[m * 80 + n] = dv;
            }
    }
}

// =====================================================================
// launcher: single fused launch
// =====================================================================
extern "C" void kernel_launch(void* const* d_in, const int* in_sizes, int n_in,
                              void* d_out, int out_size)
{
    const float* data  = (const float*)d_in[0];
    const float* emb0  = (const float*)d_in[1];
    const float* emb1  = (const float*)d_in[2];
    const float* emb2  = (const float*)d_in[3];
    const float* w1    = (const float*)d_in[4];
    const float* b1    = (const float*)d_in[5];
    const float* w2    = (const float*)d_in[6];
    const float* b2    = (const float*)d_in[7];
    const float* w3    = (const float*)d_in[8];
    const float* b3    = (const float*)d_in[9];
    const float* M     = (const float*)d_in[10];
    const float* Wg1a  = (const float*)d_in[11];
    const float* Wg1b  = (const float*)d_in[12];
    const float* Wk    = (const float*)d_in[13];
    const float* smoothing = (const float*)d_in[14];
    const float* Wg2a  = (const float*)d_in[15];
    const float* Wg2b  = (const float*)d_in[16];
    float* out = (float*)d_out;

    const int SMEM_FUSED = (3 * 64 * PZB + 80 * PXM + 16 * PZB + 16 + 16 + 80) * 4;

    cudaFuncSetAttribute(k_fused, cudaFuncAttributeMaxDynamicSharedMemorySize, SMEM_FUSED);

    k_fused<<<1025, 256, SMEM_FUSED>>>(data, emb0, emb1, emb2, w1, b1, w2, b2, w3, b3,
                                       M, Wk, smoothing, Wg1a, Wg1b, Wg2a, Wg2b, out);
}